// round 3
// baseline (speedup 1.0000x reference)
#include <cuda_runtime.h>
#include <math.h>

#define NS 128
#define NV 64
#define NVT 128             // 2*NV : channels of V / dotV
#define LATD 64
#define NNODE 10000
#define NEDGE 160000
#define FDIM 320            // NS + 3*NV
#define EPSV 1e-5f
#define INV_SQ3 0.57735026918962576451f
#define INV_SQ2 0.70710678118654752440f
#define AGG_SCALE 0.25f     // 1/sqrt(16)

// allocation-free scratch
__device__ float g_ns[NNODE * NS];
__device__ float g_nv[NNODE * NV * 3];

__device__ __forceinline__ float warp_sum(float v) {
#pragma unroll
    for (int o = 16; o > 0; o >>= 1) v += __shfl_xor_sync(0xffffffffu, v, o);
    return v;
}

// ---------------------------------------------------------------------------
// Kernel 1: per-node separate LayerNorm -> g_ns, g_nv  (one warp per node)
// ---------------------------------------------------------------------------
__global__ void __launch_bounds__(256) node_ln_kernel(
    const float* __restrict__ nf,
    const float* __restrict__ g_s, const float* __restrict__ b_s,
    const float* __restrict__ g_v)
{
    int node = blockIdx.x * 8 + (threadIdx.x >> 5);
    int lane = threadIdx.x & 31;
    if (node >= NNODE) return;
    const float* x = nf + (long)node * FDIM;

    // scalar part: mean/var over NS=128
    float s0[4];
    float sum = 0.f;
#pragma unroll
    for (int i = 0; i < 4; i++) { s0[i] = x[lane + 32 * i]; sum += s0[i]; }
    sum = warp_sum(sum);
    float mu = sum * (1.f / NS);
    float var = 0.f;
#pragma unroll
    for (int i = 0; i < 4; i++) { float d = s0[i] - mu; var += d * d; }
    var = warp_sum(var) * (1.f / NS);
    float inv = rsqrtf(var + EPSV);
#pragma unroll
    for (int i = 0; i < 4; i++) {
        int k = lane + 32 * i;
        g_ns[node * NS + k] = (s0[i] - mu) * inv * g_s[k] + b_s[k];
    }

    // vector part: NV=64 channels, vn = mean_c sum_d v^2
    float vv[6];
    float ss = 0.f;
#pragma unroll
    for (int j = 0; j < 2; j++) {
        int c = lane + 32 * j;
#pragma unroll
        for (int d = 0; d < 3; d++) { float t = x[NS + c * 3 + d]; vv[j * 3 + d] = t; ss += t * t; }
    }
    ss = warp_sum(ss) * (1.f / NV);
    float inv2 = rsqrtf(ss + EPSV);
#pragma unroll
    for (int j = 0; j < 2; j++) {
        int c = lane + 32 * j;
        float g = g_v[c];
#pragma unroll
        for (int d = 0; d < 3; d++)
            g_nv[node * (NV * 3) + c * 3 + d] = vv[j * 3 + d] * inv2 * g;
    }
}

// ---------------------------------------------------------------------------
// Kernel 2: residual  out[n] = [ nf_s @ Wr_s , einsum(nf_v, Wr_v) ]
// (also initializes the poisoned output buffer; edge kernel atomically adds)
// ---------------------------------------------------------------------------
__global__ void __launch_bounds__(256) residual_kernel(
    const float* __restrict__ nf,
    const float* __restrict__ Wr_s,
    const float* __restrict__ Wr_v,
    float* __restrict__ out)
{
    __shared__ float snf[8][FDIM];
    int base = blockIdx.x * 8;
    int tid = threadIdx.x;
    int w = tid >> 5, lane = tid & 31;
    int node = base + w;
    if (node < NNODE) {
        const float* x = nf + (long)node * FDIM;
#pragma unroll
        for (int i = 0; i < 10; i++) snf[w][lane + 32 * i] = x[lane + 32 * i];
    }
    __syncthreads();
    int nvalid = NNODE - base; if (nvalid > 8) nvalid = 8;

    for (int it = tid; it < FDIM; it += 256) {
        float acc[8];
#pragma unroll
        for (int e = 0; e < 8; e++) acc[e] = 0.f;
        if (it < NS) {
            int f = it;
            for (int k = 0; k < NS; k++) {
                float wv = Wr_s[k * NS + f];
#pragma unroll
                for (int e = 0; e < 8; e++) acc[e] += snf[e][k] * wv;
            }
        } else {
            int idx = it - NS, f = idx / 3, d = idx - 3 * f;
            for (int c = 0; c < NV; c++) {
                float wv = Wr_v[c * NV + f];
#pragma unroll
                for (int e = 0; e < 8; e++) acc[e] += snf[e][NS + c * 3 + d] * wv;
            }
        }
        for (int e = 0; e < nvalid; e++) out[(long)(base + e) * FDIM + it] = acc[e];
    }
}

// ---------------------------------------------------------------------------
// Kernel 3: fused edge kernel. 1 block = 8 edges, 256 threads.
// ---------------------------------------------------------------------------
struct alignas(16) EdgeSmem {
    float S[8][256];        // [ns[ec] | es]          (2*NS = 256)
    float V[3][8][NVT];     // per spatial dim: [nv[ec] | ev]  (2*NV = 128)
    float D[8][NVT];        // dot(V, sh1)/sqrt3      (128)
    float Lat[8][LATD];
    float Sh[8][4];
    int   Ec[8];
    float Out0[8][192];
    float P[8][64];         // S @ W_sv1
    float A[3][8][64];      // V_d @ W_vs1
    float B[3][8][64];      // V_d @ W_vv1
    float Silu[8][128];
    float Vg[8][64][3];     // gated out_v
    float S2[8][128];
    float V2[8][64][3];
    float Wenv[8][192];
};

__global__ void __launch_bounds__(256) edge_kernel(
    const float* __restrict__ latents,
    const float* __restrict__ edge_features,
    const float* __restrict__ edge_sh,
    const int*   __restrict__ edge_index,
    const int*   __restrict__ active_edges,
    const float* __restrict__ g_s_e, const float* __restrict__ b_s_e,
    const float* __restrict__ g_v_e,
    const float* __restrict__ W_ss0, const float* __restrict__ W_vv0,
    const float* __restrict__ W_sv1, const float* __restrict__ W_vs1,
    const float* __restrict__ W_vv1,
    const float* __restrict__ Wp_s,  const float* __restrict__ Wp_v,
    const float* __restrict__ W_env,
    float* __restrict__ out)
{
    extern __shared__ char smem_raw[];
    EdgeSmem& sm = *reinterpret_cast<EdgeSmem*>(smem_raw);

    int tid = threadIdx.x, w = tid >> 5, lane = tid & 31;
    int eg = blockIdx.x * 8 + w;               // grid is exactly E/8
    int ae = active_edges[eg];
    int ec = edge_index[ae];                   // row 0 of (2,E)
    if (lane == 0) sm.Ec[w] = ec;
    if (lane < 4)  sm.Sh[w][lane] = edge_sh[(long)eg * 4 + lane];
#pragma unroll
    for (int j = 0; j < 2; j++)
        sm.Lat[w][lane + 32 * j] = latents[(long)ae * LATD + lane + 32 * j];

    const float* xf = edge_features + (long)eg * FDIM;

    // --- edge scalar LN (-> S channels 128..255) ---
    {
        float s0[4];
        float sum = 0.f;
#pragma unroll
        for (int i = 0; i < 4; i++) { s0[i] = xf[lane + 32 * i]; sum += s0[i]; }
        sum = warp_sum(sum);
        float mu = sum * (1.f / NS);
        float var = 0.f;
#pragma unroll
        for (int i = 0; i < 4; i++) { float d = s0[i] - mu; var += d * d; }
        var = warp_sum(var) * (1.f / NS);
        float inv = rsqrtf(var + EPSV);
#pragma unroll
        for (int i = 0; i < 4; i++) {
            int k = lane + 32 * i;
            sm.S[w][NS + k] = (s0[i] - mu) * inv * g_s_e[k] + b_s_e[k];
        }
    }
    // --- node scalar gather (-> S channels 0..127) ---
#pragma unroll
    for (int i = 0; i < 4; i++) {
        int k = lane + 32 * i;
        sm.S[w][k] = g_ns[ec * NS + k];
    }
    // --- edge vector LN (-> V channels 64..127) ---
    {
        float vv[6];
        float ss = 0.f;
#pragma unroll
        for (int j = 0; j < 2; j++) {
            int c = lane + 32 * j;
#pragma unroll
            for (int d = 0; d < 3; d++) { float t = xf[NS + c * 3 + d]; vv[j * 3 + d] = t; ss += t * t; }
        }
        ss = warp_sum(ss) * (1.f / NV);
        float inv2 = rsqrtf(ss + EPSV);
#pragma unroll
        for (int j = 0; j < 2; j++) {
            int c = lane + 32 * j;
            float g = g_v_e[c];
#pragma unroll
            for (int d = 0; d < 3; d++)
                sm.V[d][w][NV + c] = vv[j * 3 + d] * inv2 * g;
        }
    }
    // --- node vector gather (-> V channels 0..63) ---
#pragma unroll
    for (int j = 0; j < 2; j++) {
        int c = lane + 32 * j;
#pragma unroll
        for (int d = 0; d < 3; d++)
            sm.V[d][w][c] = g_nv[ec * (NV * 3) + c * 3 + d];
    }
    __syncwarp();
    // --- dotV/sqrt3 over 128 channels ---
    {
        float s1x = sm.Sh[w][1], s1y = sm.Sh[w][2], s1z = sm.Sh[w][3];
#pragma unroll
        for (int i = 0; i < 4; i++) {
            int c = lane + 32 * i;
            sm.D[w][c] = (sm.V[0][w][c] * s1x + sm.V[1][w][c] * s1y + sm.V[2][w][c] * s1z) * INV_SQ3;
        }
    }
    __syncthreads();

    // ---- phase 1a: out0 (192 ch, warps 0-5) and P = S@W_sv1 (64 ch, warps 6-7)
    if (tid < 192) {
        int f = tid;
        float a1[8], a2[8];
#pragma unroll
        for (int e = 0; e < 8; e++) { a1[e] = 0.f; a2[e] = 0.f; }
        // S @ W_ss0 : K = 256
        for (int k = 0; k < 256; k += 4) {
            float w1[4];
#pragma unroll
            for (int q = 0; q < 4; q++) w1[q] = W_ss0[(k + q) * 192 + f];
#pragma unroll
            for (int e = 0; e < 8; e++) {
                float4 s4 = *(const float4*)&sm.S[e][k];
                a1[e] += s4.x * w1[0] + s4.y * w1[1] + s4.z * w1[2] + s4.w * w1[3];
            }
        }
        // D @ W_vv0 : K = 128
        for (int k = 0; k < NVT; k += 4) {
            float w2[4];
#pragma unroll
            for (int q = 0; q < 4; q++) w2[q] = W_vv0[(k + q) * 192 + f];
#pragma unroll
            for (int e = 0; e < 8; e++) {
                float4 d4 = *(const float4*)&sm.D[e][k];
                a2[e] += d4.x * w2[0] + d4.y * w2[1] + d4.z * w2[2] + d4.w * w2[3];
            }
        }
#pragma unroll
        for (int e = 0; e < 8; e++) sm.Out0[e][f] = sm.Sh[e][0] * a1[e] + a2[e];
    } else {
        int f = tid - 192;
        float a[8];
#pragma unroll
        for (int e = 0; e < 8; e++) a[e] = 0.f;
        for (int k = 0; k < 256; k += 4) {
            float ww[4];
#pragma unroll
            for (int q = 0; q < 4; q++) ww[q] = W_sv1[(k + q) * 64 + f];
#pragma unroll
            for (int e = 0; e < 8; e++) {
                float4 s4 = *(const float4*)&sm.S[e][k];
                a[e] += s4.x * ww[0] + s4.y * ww[1] + s4.z * ww[2] + s4.w * ww[3];
            }
        }
#pragma unroll
        for (int e = 0; e < 8; e++) sm.P[e][f] = a[e];
    }

    // ---- phase 1b: A_d = V_d@W_vs1, B_d = V_d@W_vv1 (3x64 ch on warps 0-5), K=128
    if (tid < 192) {
        int d = tid >> 6, f = tid & 63;
        float aa[8], ab[8];
#pragma unroll
        for (int e = 0; e < 8; e++) { aa[e] = 0.f; ab[e] = 0.f; }
        for (int k = 0; k < NVT; k += 4) {
            float wa[4], wb[4];
#pragma unroll
            for (int q = 0; q < 4; q++) {
                wa[q] = W_vs1[(k + q) * 64 + f];
                wb[q] = W_vv1[(k + q) * 64 + f];
            }
#pragma unroll
            for (int e = 0; e < 8; e++) {
                float4 v4 = *(const float4*)&sm.V[d][e][k];
                aa[e] += v4.x * wa[0] + v4.y * wa[1] + v4.z * wa[2] + v4.w * wa[3];
                ab[e] += v4.x * wb[0] + v4.y * wb[1] + v4.z * wb[2] + v4.w * wb[3];
            }
        }
#pragma unroll
        for (int e = 0; e < 8; e++) { sm.A[d][e][f] = aa[e]; sm.B[d][e][f] = ab[e]; }
    }
    __syncthreads();

    // ---- phase 1c: silu, gates, gated out_v
    for (int it = tid; it < 8 * 128; it += 256) {
        int e = it >> 7, k = it & 127;
        float x = sm.Out0[e][k];
        sm.Silu[e][k] = x / (1.f + expf(-x));
    }
    for (int it = tid; it < 8 * 64; it += 256) {
        int e = it >> 6, f = it & 63;
        float g = 1.f / (1.f + expf(-sm.Out0[e][128 + f]));
        float sh0 = sm.Sh[e][0];
        float s1x = sm.Sh[e][1], s1y = sm.Sh[e][2], s1z = sm.Sh[e][3];
        float p  = sm.P[e][f];
        float a0 = sm.A[0][e][f], a1 = sm.A[1][e][f], a2 = sm.A[2][e][f];
        float b0 = sm.B[0][e][f], b1 = sm.B[1][e][f], b2 = sm.B[2][e][f];
        float ov0 = p * s1x + a0 * sh0 + (b1 * s1z - b2 * s1y) * INV_SQ2;
        float ov1 = p * s1y + a1 * sh0 + (b2 * s1x - b0 * s1z) * INV_SQ2;
        float ov2 = p * s1z + a2 * sh0 + (b0 * s1y - b1 * s1x) * INV_SQ2;
        sm.Vg[e][f][0] = ov0 * g;
        sm.Vg[e][f][1] = ov1 * g;
        sm.Vg[e][f][2] = ov2 * g;
    }
    __syncthreads();

    // ---- phase 1d: S2 = silu@Wp_s, V2 = Vg@Wp_v, Wenv = lat@W_env
    for (int it = tid; it < 512; it += 256) {
        float acc[8];
#pragma unroll
        for (int e = 0; e < 8; e++) acc[e] = 0.f;
        if (it < 128) {
            int f = it;
            for (int k = 0; k < 128; k++) {
                float wv = Wp_s[k * 128 + f];
#pragma unroll
                for (int e = 0; e < 8; e++) acc[e] += sm.Silu[e][k] * wv;
            }
#pragma unroll
            for (int e = 0; e < 8; e++) sm.S2[e][f] = acc[e];
        } else if (it < 320) {
            int idx = it - 128, d = idx >> 6, f = idx & 63;
            for (int c = 0; c < 64; c++) {
                float wv = Wp_v[c * 64 + f];
#pragma unroll
                for (int e = 0; e < 8; e++) acc[e] += sm.Vg[e][c][d] * wv;
            }
#pragma unroll
            for (int e = 0; e < 8; e++) sm.V2[e][f][d] = acc[e];
        } else {
            int f = it - 320;
            for (int k = 0; k < LATD; k++) {
                float wv = W_env[k * 192 + f];
#pragma unroll
                for (int e = 0; e < 8; e++) acc[e] += sm.Lat[e][k] * wv;
            }
#pragma unroll
            for (int e = 0; e < 8; e++) sm.Wenv[e][f] = acc[e];
        }
    }
    __syncthreads();

    // ---- phase 1e: scale by env weights and scatter (segment_sum via atomics)
    for (int it = tid; it < 8 * FDIM; it += 256) {
        int e = it / FDIM, k = it - e * FDIM;
        int node = sm.Ec[e];
        float val;
        if (k < NS) {
            val = sm.S2[e][k] * sm.Wenv[e][k];
        } else {
            int idx = k - NS;
            int f = idx / 3, d = idx - 3 * f;
            val = sm.V2[e][f][d] * sm.Wenv[e][NS + f];
        }
        atomicAdd(&out[(long)node * FDIM + k], AGG_SCALE * val);
    }
}

// ---------------------------------------------------------------------------
extern "C" void kernel_launch(void* const* d_in, const int* in_sizes, int n_in,
                              void* d_out, int out_size)
{
    const float* latents       = (const float*)d_in[0];
    const float* node_features = (const float*)d_in[1];
    const float* edge_features = (const float*)d_in[2];
    const float* edge_sh       = (const float*)d_in[3];
    const int*   edge_index    = (const int*)  d_in[4];
    /* d_in[5] atom_type unused */
    const int*   active_edges  = (const int*)  d_in[6];
    const float* g_s_n = (const float*)d_in[7];
    const float* b_s_n = (const float*)d_in[8];
    const float* g_v_n = (const float*)d_in[9];
    const float* g_s_e = (const float*)d_in[10];
    const float* b_s_e = (const float*)d_in[11];
    const float* g_v_e = (const float*)d_in[12];
    const float* W_ss0 = (const float*)d_in[13];
    const float* W_vv0 = (const float*)d_in[14];
    const float* W_sv1 = (const float*)d_in[15];
    const float* W_vs1 = (const float*)d_in[16];
    const float* W_vv1 = (const float*)d_in[17];
    const float* Wp_s  = (const float*)d_in[18];
    const float* Wp_v  = (const float*)d_in[19];
    const float* W_env = (const float*)d_in[20];
    const float* Wr_s  = (const float*)d_in[21];
    const float* Wr_v  = (const float*)d_in[22];
    float* out = (float*)d_out;

    cudaFuncSetAttribute(edge_kernel, cudaFuncAttributeMaxDynamicSharedMemorySize,
                         (int)sizeof(EdgeSmem));

    node_ln_kernel<<<(NNODE + 7) / 8, 256>>>(node_features, g_s_n, b_s_n, g_v_n);
    residual_kernel<<<(NNODE + 7) / 8, 256>>>(node_features, Wr_s, Wr_v, out);
    edge_kernel<<<NEDGE / 8, 256, sizeof(EdgeSmem)>>>(
        latents, edge_features, edge_sh, edge_index, active_edges,
        g_s_e, b_s_e, g_v_e,
        W_ss0, W_vv0, W_sv1, W_vs1, W_vv1,
        Wp_s, Wp_v, W_env, out);
}

// round 7
// speedup vs baseline: 1.9232x; 1.9232x over previous
#include <cuda_runtime.h>
#include <cuda_bf16.h>
#include <math.h>
#include <stdint.h>

#define NS 128
#define NV 64
#define LATD 64
#define NNODE 10000
#define EDG 160000
#define FDIM 320
#define EPSV 1e-5f
#define INV_SQ3 0.57735026918962576451f
#define INV_SQ2 0.70710678118654752440f
#define AGG_SCALE 0.25f

// ---------------------------------------------------------------------------
// helpers
// ---------------------------------------------------------------------------
__device__ __forceinline__ uint32_t smem_u32(const void* p) {
    uint32_t a;
    asm("{ .reg .u64 t; cvta.to.shared.u64 t, %1; cvt.u32.u64 %0, t; }" : "=r"(a) : "l"(p));
    return a;
}
__device__ __forceinline__ float warp_sum(float v) {
#pragma unroll
    for (int o = 16; o > 0; o >>= 1) v += __shfl_xor_sync(0xffffffffu, v, o);
    return v;
}
__device__ __forceinline__ void bsplit(float x, __nv_bfloat16* ph, __nv_bfloat16* pl) {
    __nv_bfloat16 h = __float2bfloat16_rn(x);
    *ph = h;
    *pl = __float2bfloat16_rn(x - __bfloat162float(h));
}
__device__ __forceinline__ void cvt_pair(float2 v, uint32_t& hi, uint32_t& lo) {
    __nv_bfloat162 H, L;
    H.x = __float2bfloat16_rn(v.x);
    H.y = __float2bfloat16_rn(v.y);
    L.x = __float2bfloat16_rn(v.x - __bfloat162float(H.x));
    L.y = __float2bfloat16_rn(v.y - __bfloat162float(H.y));
    hi = *reinterpret_cast<uint32_t*>(&H);
    lo = *reinterpret_cast<uint32_t*>(&L);
}
__device__ __forceinline__ void mma_bf16(float* d, const uint32_t* a, uint32_t b0, uint32_t b1) {
    asm volatile("mma.sync.aligned.m16n8k16.row.col.f32.bf16.bf16.f32 "
        "{%0,%1,%2,%3}, {%4,%5,%6,%7}, {%8,%9}, {%0,%1,%2,%3};"
        : "+f"(d[0]), "+f"(d[1]), "+f"(d[2]), "+f"(d[3])
        : "r"(a[0]), "r"(a[1]), "r"(a[2]), "r"(a[3]), "r"(b0), "r"(b1));
}

// ---------------------------------------------------------------------------
// Global scratch (allocation-free)
// ---------------------------------------------------------------------------
__device__ float g_ns[NNODE * NS];
__device__ float g_nv[NNODE * NV * 3];

__device__ float g_S[(size_t)EDG * 256];       // A of GEMM1
__device__ float g_D[(size_t)EDG * 128];       // A of GEMM2
__device__ float g_V[(size_t)3 * EDG * 128];   // A of GEMM3 (d-major rows)
__device__ float g_L[(size_t)EDG * 64];        // A of GEMM6
__device__ float g_U[(size_t)EDG * 128];       // A of GEMM4 (silu)
__device__ float g_G[(size_t)3 * EDG * 64];    // A of GEMM5 (gated v)

__device__ float g_C1[(size_t)EDG * 256];      // [out0s(192) | P(64)]
__device__ float g_C2[(size_t)EDG * 192];      // out0d
__device__ float g_C3[(size_t)3 * EDG * 128];  // [Av(64) | Aw(64)] per d
__device__ float g_S2[(size_t)EDG * 128];
__device__ float g_V2[(size_t)3 * EDG * 64];
__device__ float g_We[(size_t)EDG * 192];

// B matrices bf16 [N x K] hi/lo
__device__ __nv_bfloat16 gB1h[256 * 256], gB1l[256 * 256];
__device__ __nv_bfloat16 gB2h[192 * 128], gB2l[192 * 128];
__device__ __nv_bfloat16 gB3h[128 * 128], gB3l[128 * 128];
__device__ __nv_bfloat16 gBDh[128 * 128], gBDl[128 * 128];
__device__ __nv_bfloat16 gBEh[64 * 64],   gBEl[64 * 64];
__device__ __nv_bfloat16 gBFh[192 * 64],  gBFl[192 * 64];

// ---------------------------------------------------------------------------
__global__ void build_B(const float* __restrict__ Wa, const float* __restrict__ Wb,
                        int Na, int Nb, int K,
                        __nv_bfloat16* __restrict__ dh, __nv_bfloat16* __restrict__ dl)
{
    int N = Na + Nb;
    for (int idx = blockIdx.x * blockDim.x + threadIdx.x; idx < N * K; idx += gridDim.x * blockDim.x) {
        int n = idx / K, k = idx - n * K;
        float w = (n < Na) ? Wa[(size_t)k * Na + n] : Wb[(size_t)k * Nb + (n - Na)];
        bsplit(w, &dh[idx], &dl[idx]);
    }
}

// ---------------------------------------------------------------------------
// Split-bf16 mma.sync GEMM:  C[M x N] = A[M x K](fp32) @ B[N x K]^T
// Block: 256 thr = 8 warps x 16 rows (M-tile 128). grid.y covers N in NT chunks.
// ---------------------------------------------------------------------------
template <int N, int NT, int K>
__global__ void __launch_bounds__(256) gemm_mma(
    const float* __restrict__ A,
    const __nv_bfloat16* __restrict__ Bh,
    const __nv_bfloat16* __restrict__ Bl,
    float* __restrict__ C)
{
    constexpr int KP = K + 8;           // pad: bank-conflict-free ldmatrix
    constexpr int NTILES = NT / 8;
    constexpr int NGRP = NT / 16;
    extern __shared__ __nv_bfloat16 sB[];
    __nv_bfloat16* sBh = sB;
    __nv_bfloat16* sBl = sB + NT * KP;

    int tid = threadIdx.x;
    int wm = tid >> 5, lane = tid & 31;
    int n0 = blockIdx.y * NT;
    size_t m0 = (size_t)blockIdx.x * 128;

    // stage B hi/lo into padded SMEM
    for (int i = tid; i < NT * (K / 8); i += 256) {
        int n = i / (K / 8), kc = (i - n * (K / 8)) * 8;
        *(uint4*)&sBh[n * KP + kc] = *(const uint4*)&Bh[(size_t)(n0 + n) * K + kc];
        *(uint4*)&sBl[n * KP + kc] = *(const uint4*)&Bl[(size_t)(n0 + n) * K + kc];
    }
    __syncthreads();

    float acc[NTILES][4];
#pragma unroll
    for (int t = 0; t < NTILES; t++)
#pragma unroll
        for (int j = 0; j < 4; j++) acc[t][j] = 0.f;

    int q = lane & 3, rr = lane >> 2;
    const float* A0 = A + (m0 + wm * 16 + rr) * K + q * 2;
    const float* A1 = A0 + 8 * K;

    // ldmatrix lane address components (matrix m = lane>>3, row r = lane&7)
    int lmrow = ((lane >> 4) << 3) + (lane & 7);     // (m/2)*8 + r
    int lmk = ((lane >> 3) & 1) * 8;                 // (m&1)*8
    uint32_t baseh = smem_u32(sBh) + (uint32_t)(lmrow * KP + lmk) * 2;
    uint32_t basel = smem_u32(sBl) + (uint32_t)(lmrow * KP + lmk) * 2;

    float2 xc[4];
    xc[0] = *(const float2*)(A0);
    xc[1] = *(const float2*)(A1);
    xc[2] = *(const float2*)(A0 + 8);
    xc[3] = *(const float2*)(A1 + 8);

#pragma unroll 4
    for (int k0 = 0; k0 < K; k0 += 16) {
        int kn = (k0 + 16 < K) ? (k0 + 16) : k0;
        float2 xn[4];
        xn[0] = *(const float2*)(A0 + kn);
        xn[1] = *(const float2*)(A1 + kn);
        xn[2] = *(const float2*)(A0 + kn + 8);
        xn[3] = *(const float2*)(A1 + kn + 8);

        uint32_t ah[4], al[4];
#pragma unroll
        for (int j = 0; j < 4; j++) cvt_pair(xc[j], ah[j], al[j]);

#pragma unroll
        for (int g = 0; g < NGRP; g++) {
            uint32_t bh0, bh1, bh2, bh3, bl0, bl1, bl2, bl3;
            uint32_t adh = baseh + (uint32_t)(g * 16 * KP + k0) * 2;
            uint32_t adl = basel + (uint32_t)(g * 16 * KP + k0) * 2;
            asm volatile("ldmatrix.sync.aligned.m8n8.x4.shared.b16 {%0,%1,%2,%3}, [%4];"
                : "=r"(bh0), "=r"(bh1), "=r"(bh2), "=r"(bh3) : "r"(adh));
            asm volatile("ldmatrix.sync.aligned.m8n8.x4.shared.b16 {%0,%1,%2,%3}, [%4];"
                : "=r"(bl0), "=r"(bl1), "=r"(bl2), "=r"(bl3) : "r"(adl));
            mma_bf16(acc[2 * g], ah, bh0, bh1);
            mma_bf16(acc[2 * g], ah, bl0, bl1);
            mma_bf16(acc[2 * g], al, bh0, bh1);
            mma_bf16(acc[2 * g + 1], ah, bh2, bh3);
            mma_bf16(acc[2 * g + 1], ah, bl2, bl3);
            mma_bf16(acc[2 * g + 1], al, bh2, bh3);
        }
#pragma unroll
        for (int j = 0; j < 4; j++) xc[j] = xn[j];
    }

    size_t r = m0 + wm * 16 + rr;
#pragma unroll
    for (int t = 0; t < NTILES; t++) {
        int col = n0 + t * 8 + q * 2;
        *(float2*)&C[r * N + col] = make_float2(acc[t][0], acc[t][1]);
        *(float2*)&C[(r + 8) * N + col] = make_float2(acc[t][2], acc[t][3]);
    }
}

// ---------------------------------------------------------------------------
// node LN
// ---------------------------------------------------------------------------
__global__ void __launch_bounds__(256) node_ln_kernel(
    const float* __restrict__ nf,
    const float* __restrict__ g_s, const float* __restrict__ b_s,
    const float* __restrict__ g_v)
{
    int node = blockIdx.x * 8 + (threadIdx.x >> 5);
    int lane = threadIdx.x & 31;
    if (node >= NNODE) return;
    const float* x = nf + (size_t)node * FDIM;

    float s0[4], sum = 0.f;
#pragma unroll
    for (int i = 0; i < 4; i++) { s0[i] = x[lane + 32 * i]; sum += s0[i]; }
    sum = warp_sum(sum);
    float mu = sum * (1.f / NS), var = 0.f;
#pragma unroll
    for (int i = 0; i < 4; i++) { float d = s0[i] - mu; var += d * d; }
    var = warp_sum(var) * (1.f / NS);
    float inv = rsqrtf(var + EPSV);
#pragma unroll
    for (int i = 0; i < 4; i++) {
        int k = lane + 32 * i;
        g_ns[node * NS + k] = (s0[i] - mu) * inv * g_s[k] + b_s[k];
    }
    float vv[6], ss = 0.f;
#pragma unroll
    for (int j = 0; j < 2; j++) {
        int cc = lane + 32 * j;
#pragma unroll
        for (int d = 0; d < 3; d++) { float t = x[NS + cc * 3 + d]; vv[j * 3 + d] = t; ss += t * t; }
    }
    ss = warp_sum(ss) * (1.f / NV);
    float inv2 = rsqrtf(ss + EPSV);
#pragma unroll
    for (int j = 0; j < 2; j++) {
        int cc = lane + 32 * j;
        float g = g_v[cc];
#pragma unroll
        for (int d = 0; d < 3; d++)
            g_nv[node * (NV * 3) + cc * 3 + d] = vv[j * 3 + d] * inv2 * g;
    }
}

// ---------------------------------------------------------------------------
// residual (initializes out)
// ---------------------------------------------------------------------------
__global__ void __launch_bounds__(256) residual_kernel(
    const float* __restrict__ nf, const float* __restrict__ Wr_s,
    const float* __restrict__ Wr_v, float* __restrict__ out)
{
    __shared__ float snf[8][FDIM];
    int base = blockIdx.x * 8, tid = threadIdx.x;
    int w = tid >> 5, lane = tid & 31;
    int node = base + w;
    if (node < NNODE) {
        const float* x = nf + (size_t)node * FDIM;
#pragma unroll
        for (int i = 0; i < 10; i++) snf[w][lane + 32 * i] = x[lane + 32 * i];
    }
    __syncthreads();
    int nvalid = NNODE - base; if (nvalid > 8) nvalid = 8;
    for (int it = tid; it < FDIM; it += 256) {
        float acc[8];
#pragma unroll
        for (int e = 0; e < 8; e++) acc[e] = 0.f;
        if (it < NS) {
            for (int k = 0; k < NS; k++) {
                float wv = Wr_s[k * NS + it];
#pragma unroll
                for (int e = 0; e < 8; e++) acc[e] += snf[e][k] * wv;
            }
        } else {
            int idx = it - NS, f = idx / 3, d = idx - 3 * f;
            for (int cc = 0; cc < NV; cc++) {
                float wv = Wr_v[cc * NV + f];
#pragma unroll
                for (int e = 0; e < 8; e++) acc[e] += snf[e][NS + cc * 3 + d] * wv;
            }
        }
        for (int e = 0; e < nvalid; e++) out[(size_t)(base + e) * FDIM + it] = acc[e];
    }
}

// ---------------------------------------------------------------------------
// prep: edge LN + gathers -> fp32 A matrices (one warp per edge)
// ---------------------------------------------------------------------------
__global__ void __launch_bounds__(256) prep_kernel(
    const float* __restrict__ latents, const float* __restrict__ edge_features,
    const float* __restrict__ edge_sh, const int* __restrict__ edge_index,
    const int* __restrict__ active_edges,
    const float* __restrict__ g_s_e, const float* __restrict__ b_s_e,
    const float* __restrict__ g_v_e)
{
    int e = blockIdx.x * 8 + (threadIdx.x >> 5);
    int lane = threadIdx.x & 31;
    int ae = active_edges[e];
    int ec = edge_index[ae];
    const float* xf = edge_features + (size_t)e * FDIM;

    float sx = edge_sh[(size_t)e * 4 + 1];
    float sy = edge_sh[(size_t)e * 4 + 2];
    float sz = edge_sh[(size_t)e * 4 + 3];

    // scalar LN -> S[128..255]
    {
        float s0[4], sum = 0.f;
#pragma unroll
        for (int i = 0; i < 4; i++) { s0[i] = xf[lane + 32 * i]; sum += s0[i]; }
        sum = warp_sum(sum);
        float mu = sum * (1.f / NS), var = 0.f;
#pragma unroll
        for (int i = 0; i < 4; i++) { float d = s0[i] - mu; var += d * d; }
        var = warp_sum(var) * (1.f / NS);
        float inv = rsqrtf(var + EPSV);
#pragma unroll
        for (int i = 0; i < 4; i++) {
            int k = lane + 32 * i;
            g_S[(size_t)e * 256 + 128 + k] = (s0[i] - mu) * inv * g_s_e[k] + b_s_e[k];
        }
    }
    // node scalar gather -> S[0..127]
#pragma unroll
    for (int i = 0; i < 4; i++) {
        int k = lane + 32 * i;
        g_S[(size_t)e * 256 + k] = g_ns[ec * NS + k];
    }
    // edge vector LN -> V[.., 64..127]; node gather -> V[.., 0..63]
    float ev[2][3], nvv[2][3];
    {
        float ss = 0.f;
#pragma unroll
        for (int j = 0; j < 2; j++) {
            int cc = lane + 32 * j;
#pragma unroll
            for (int d = 0; d < 3; d++) { float t = xf[NS + cc * 3 + d]; ev[j][d] = t; ss += t * t; }
        }
        ss = warp_sum(ss) * (1.f / NV);
        float inv2 = rsqrtf(ss + EPSV);
#pragma unroll
        for (int j = 0; j < 2; j++) {
            int cc = lane + 32 * j;
            float g = g_v_e[cc];
#pragma unroll
            for (int d = 0; d < 3; d++) {
                ev[j][d] = ev[j][d] * inv2 * g;
                g_V[((size_t)d * EDG + e) * 128 + 64 + cc] = ev[j][d];
            }
        }
    }
#pragma unroll
    for (int j = 0; j < 2; j++) {
        int cc = lane + 32 * j;
#pragma unroll
        for (int d = 0; d < 3; d++) {
            nvv[j][d] = g_nv[ec * (NV * 3) + cc * 3 + d];
            g_V[((size_t)d * EDG + e) * 128 + cc] = nvv[j][d];
        }
    }
    // D = dot(V, sh1)/sqrt3
#pragma unroll
    for (int j = 0; j < 2; j++) {
        int cc = lane + 32 * j;
        g_D[(size_t)e * 128 + cc]      = (nvv[j][0] * sx + nvv[j][1] * sy + nvv[j][2] * sz) * INV_SQ3;
        g_D[(size_t)e * 128 + 64 + cc] = (ev[j][0] * sx + ev[j][1] * sy + ev[j][2] * sz) * INV_SQ3;
    }
    // latent gather
#pragma unroll
    for (int j = 0; j < 2; j++) {
        int k = lane + 32 * j;
        g_L[(size_t)e * 64 + k] = latents[(size_t)ae * LATD + k];
    }
}

// ---------------------------------------------------------------------------
// nonlin: combine GEMM outputs -> Silu (g_U) + gated Vg (g_G)
// ---------------------------------------------------------------------------
__global__ void __launch_bounds__(256) nonlin_kernel(const float* __restrict__ edge_sh)
{
    int e = blockIdx.x * 8 + (threadIdx.x >> 5);
    int lane = threadIdx.x & 31;
    float sh0 = edge_sh[(size_t)e * 4 + 0];
    float sx = edge_sh[(size_t)e * 4 + 1];
    float sy = edge_sh[(size_t)e * 4 + 2];
    float sz = edge_sh[(size_t)e * 4 + 3];

    float gate[2];
#pragma unroll
    for (int i = 0; i < 6; i++) {
        int f = lane + 32 * i;
        float o = sh0 * g_C1[(size_t)e * 256 + f] + g_C2[(size_t)e * 192 + f];
        if (i < 4) {
            g_U[(size_t)e * 128 + f] = o / (1.f + expf(-o));
        } else {
            gate[i - 4] = 1.f / (1.f + expf(-o));
        }
    }
#pragma unroll
    for (int j = 0; j < 2; j++) {
        int f = lane + 32 * j;
        float P = g_C1[(size_t)e * 256 + 192 + f];
        float Av[3], Aw[3];
#pragma unroll
        for (int d = 0; d < 3; d++) {
            size_t r = ((size_t)d * EDG + e) * 128;
            Av[d] = g_C3[r + f];
            Aw[d] = g_C3[r + 64 + f];
        }
        float g = gate[j];
        float ov0 = (P * sx + sh0 * Av[0] + (Aw[1] * sz - Aw[2] * sy) * INV_SQ2) * g;
        float ov1 = (P * sy + sh0 * Av[1] + (Aw[2] * sx - Aw[0] * sz) * INV_SQ2) * g;
        float ov2 = (P * sz + sh0 * Av[2] + (Aw[0] * sy - Aw[1] * sx) * INV_SQ2) * g;
        g_G[((size_t)0 * EDG + e) * 64 + f] = ov0;
        g_G[((size_t)1 * EDG + e) * 64 + f] = ov1;
        g_G[((size_t)2 * EDG + e) * 64 + f] = ov2;
    }
}

// ---------------------------------------------------------------------------
// final: env-scale + atomic scatter
// ---------------------------------------------------------------------------
__global__ void __launch_bounds__(256) final_kernel(
    const int* __restrict__ edge_index, const int* __restrict__ active_edges,
    float* __restrict__ out)
{
    int e = blockIdx.x * 8 + (threadIdx.x >> 5);
    int lane = threadIdx.x & 31;
    int ec = edge_index[active_edges[e]];
    float* dst = out + (size_t)ec * FDIM;
#pragma unroll
    for (int i = 0; i < 4; i++) {
        int k = lane + 32 * i;
        float v = g_S2[(size_t)e * 128 + k] * g_We[(size_t)e * 192 + k];
        atomicAdd(&dst[k], AGG_SCALE * v);
    }
#pragma unroll
    for (int j = 0; j < 2; j++) {
        int f = lane + 32 * j;
        float wv = g_We[(size_t)e * 192 + 128 + f];
#pragma unroll
        for (int d = 0; d < 3; d++) {
            float v = g_V2[((size_t)d * EDG + e) * 64 + f] * wv;
            atomicAdd(&dst[NS + f * 3 + d], AGG_SCALE * v);
        }
    }
}

// ---------------------------------------------------------------------------
extern "C" void kernel_launch(void* const* d_in, const int* in_sizes, int n_in,
                              void* d_out, int out_size)
{
    const float* latents       = (const float*)d_in[0];
    const float* node_features = (const float*)d_in[1];
    const float* edge_features = (const float*)d_in[2];
    const float* edge_sh       = (const float*)d_in[3];
    const int*   edge_index    = (const int*)  d_in[4];
    const int*   active_edges  = (const int*)  d_in[6];
    const float* g_s_n = (const float*)d_in[7];
    const float* b_s_n = (const float*)d_in[8];
    const float* g_v_n = (const float*)d_in[9];
    const float* g_s_e = (const float*)d_in[10];
    const float* b_s_e = (const float*)d_in[11];
    const float* g_v_e = (const float*)d_in[12];
    const float* W_ss0 = (const float*)d_in[13];
    const float* W_vv0 = (const float*)d_in[14];
    const float* W_sv1 = (const float*)d_in[15];
    const float* W_vs1 = (const float*)d_in[16];
    const float* W_vv1 = (const float*)d_in[17];
    const float* Wp_s  = (const float*)d_in[18];
    const float* Wp_v  = (const float*)d_in[19];
    const float* W_env = (const float*)d_in[20];
    const float* Wr_s  = (const float*)d_in[21];
    const float* Wr_v  = (const float*)d_in[22];
    float* out = (float*)d_out;

    __nv_bfloat16 *B1h, *B1l, *B2h, *B2l, *B3h, *B3l, *BDh, *BDl, *BEh, *BEl, *BFh, *BFl;
    cudaGetSymbolAddress((void**)&B1h, gB1h); cudaGetSymbolAddress((void**)&B1l, gB1l);
    cudaGetSymbolAddress((void**)&B2h, gB2h); cudaGetSymbolAddress((void**)&B2l, gB2l);
    cudaGetSymbolAddress((void**)&B3h, gB3h); cudaGetSymbolAddress((void**)&B3l, gB3l);
    cudaGetSymbolAddress((void**)&BDh, gBDh); cudaGetSymbolAddress((void**)&BDl, gBDl);
    cudaGetSymbolAddress((void**)&BEh, gBEh); cudaGetSymbolAddress((void**)&BEl, gBEl);
    cudaGetSymbolAddress((void**)&BFh, gBFh); cudaGetSymbolAddress((void**)&BFl, gBFl);
    float *Sf, *Df, *Vf, *Lf, *Uf, *Gf, *C1, *C2, *C3, *S2, *V2, *We;
    cudaGetSymbolAddress((void**)&Sf, g_S); cudaGetSymbolAddress((void**)&Df, g_D);
    cudaGetSymbolAddress((void**)&Vf, g_V); cudaGetSymbolAddress((void**)&Lf, g_L);
    cudaGetSymbolAddress((void**)&Uf, g_U); cudaGetSymbolAddress((void**)&Gf, g_G);
    cudaGetSymbolAddress((void**)&C1, g_C1); cudaGetSymbolAddress((void**)&C2, g_C2);
    cudaGetSymbolAddress((void**)&C3, g_C3); cudaGetSymbolAddress((void**)&S2, g_S2);
    cudaGetSymbolAddress((void**)&V2, g_V2); cudaGetSymbolAddress((void**)&We, g_We);

    // dynamic SMEM sizes: 2 * NT * (K+8) * 2 bytes
    const int SM1 = 2 * 128 * 264 * 2;  // 135168
    const int SM2 = 2 * 96 * 136 * 2;   // 52224
    const int SM3 = 2 * 128 * 136 * 2;  // 69632
    const int SM5 = 2 * 64 * 72 * 2;    // 18432
    const int SM6 = 2 * 96 * 72 * 2;    // 27648
    cudaFuncSetAttribute(gemm_mma<256, 128, 256>, cudaFuncAttributeMaxDynamicSharedMemorySize, SM1);
    cudaFuncSetAttribute(gemm_mma<192, 96, 128>,  cudaFuncAttributeMaxDynamicSharedMemorySize, SM2);
    cudaFuncSetAttribute(gemm_mma<128, 128, 128>, cudaFuncAttributeMaxDynamicSharedMemorySize, SM3);
    cudaFuncSetAttribute(gemm_mma<64, 64, 64>,    cudaFuncAttributeMaxDynamicSharedMemorySize, SM5);
    cudaFuncSetAttribute(gemm_mma<192, 96, 64>,   cudaFuncAttributeMaxDynamicSharedMemorySize, SM6);

    build_B<<<64, 256>>>(W_ss0, W_sv1, 192, 64, 256, B1h, B1l);
    build_B<<<64, 256>>>(W_vv0, nullptr, 192, 0, 128, B2h, B2l);
    build_B<<<64, 256>>>(W_vs1, W_vv1, 64, 64, 128, B3h, B3l);
    build_B<<<64, 256>>>(Wp_s, nullptr, 128, 0, 128, BDh, BDl);
    build_B<<<64, 256>>>(Wp_v, nullptr, 64, 0, 64, BEh, BEl);
    build_B<<<64, 256>>>(W_env, nullptr, 192, 0, 64, BFh, BFl);

    node_ln_kernel<<<(NNODE + 7) / 8, 256>>>(node_features, g_s_n, b_s_n, g_v_n);
    residual_kernel<<<(NNODE + 7) / 8, 256>>>(node_features, Wr_s, Wr_v, out);
    prep_kernel<<<EDG / 8, 256>>>(latents, edge_features, edge_sh, edge_index, active_edges,
                                  g_s_e, b_s_e, g_v_e);

    gemm_mma<256, 128, 256><<<dim3(EDG / 128, 2), 256, SM1>>>(Sf, B1h, B1l, C1);
    gemm_mma<192, 96, 128><<<dim3(EDG / 128, 2), 256, SM2>>>(Df, B2h, B2l, C2);
    gemm_mma<128, 128, 128><<<dim3(3 * EDG / 128, 1), 256, SM3>>>(Vf, B3h, B3l, C3);

    nonlin_kernel<<<EDG / 8, 256>>>(edge_sh);

    gemm_mma<128, 128, 128><<<dim3(EDG / 128, 1), 256, SM3>>>(Uf, BDh, BDl, S2);
    gemm_mma<64, 64, 64><<<dim3(3 * EDG / 128, 1), 256, SM5>>>(Gf, BEh, BEl, V2);
    gemm_mma<192, 96, 64><<<dim3(EDG / 128, 2), 256, SM6>>>(Lf, BFh, BFl, We);

    final_kernel<<<EDG / 8, 256>>>(edge_index, active_edges, out);
}

// round 8
// speedup vs baseline: 2.3224x; 1.2076x over previous
#include <cuda_runtime.h>
#include <cuda_bf16.h>
#include <math.h>
#include <stdint.h>

#define NS 128
#define NV 64
#define LATD 64
#define NNODE 10000
#define EDG 160000
#define FDIM 320
#define EPSV 1e-5f
#define INV_SQ3 0.57735026918962576451f
#define INV_SQ2 0.70710678118654752440f
#define AGG_SCALE 0.25f

// ---------------------------------------------------------------------------
__device__ __forceinline__ uint32_t smem_u32(const void* p) {
    uint32_t a;
    asm("{ .reg .u64 t; cvta.to.shared.u64 t, %1; cvt.u32.u64 %0, t; }" : "=r"(a) : "l"(p));
    return a;
}
__device__ __forceinline__ float warp_sum(float v) {
#pragma unroll
    for (int o = 16; o > 0; o >>= 1) v += __shfl_xor_sync(0xffffffffu, v, o);
    return v;
}
__device__ __forceinline__ void bsplit(float x, __nv_bfloat16* ph, __nv_bfloat16* pl) {
    __nv_bfloat16 h = __float2bfloat16_rn(x);
    *ph = h;
    *pl = __float2bfloat16_rn(x - __bfloat162float(h));
}
// split a float2 into bf16x2 hi / bf16x2 lo
__device__ __forceinline__ void bsplit2(float a, float b, __nv_bfloat162* H, __nv_bfloat162* L) {
    __nv_bfloat162 h, l;
    h.x = __float2bfloat16_rn(a);
    h.y = __float2bfloat16_rn(b);
    l.x = __float2bfloat16_rn(a - __bfloat162float(h.x));
    l.y = __float2bfloat16_rn(b - __bfloat162float(h.y));
    *H = h; *L = l;
}
__device__ __forceinline__ void mma_bf16(float* d, const uint32_t* a, uint32_t b0, uint32_t b1) {
    asm volatile("mma.sync.aligned.m16n8k16.row.col.f32.bf16.bf16.f32 "
        "{%0,%1,%2,%3}, {%4,%5,%6,%7}, {%8,%9}, {%0,%1,%2,%3};"
        : "+f"(d[0]), "+f"(d[1]), "+f"(d[2]), "+f"(d[3])
        : "r"(a[0]), "r"(a[1]), "r"(a[2]), "r"(a[3]), "r"(b0), "r"(b1));
}

// ---------------------------------------------------------------------------
// Global scratch (allocation-free)
// ---------------------------------------------------------------------------
__device__ float g_ns[NNODE * NS];
__device__ float g_nv[NNODE * NV * 3];
__device__ int   g_ec[EDG];

// A matrices, pre-split bf16 hi/lo
__device__ __nv_bfloat16 g_Sh[(size_t)EDG * 128], g_Sl[(size_t)EDG * 128];   // es
__device__ __nv_bfloat16 g_Dh[(size_t)EDG * 128], g_Dl[(size_t)EDG * 128];   // dotV
__device__ __nv_bfloat16 g_Vh[(size_t)3 * EDG * 64], g_Vl[(size_t)3 * EDG * 64]; // ev d-major
__device__ __nv_bfloat16 g_Lh[(size_t)EDG * 64],  g_Ll[(size_t)EDG * 64];    // latents
__device__ __nv_bfloat16 g_Uh[(size_t)EDG * 128], g_Ul[(size_t)EDG * 128];   // silu
__device__ __nv_bfloat16 g_Gh[(size_t)3 * EDG * 64], g_Gl[(size_t)3 * EDG * 64]; // gated v

// node tables (fp32, L2-resident)
__device__ float g_T1[(size_t)NNODE * 256];          // ns @ [W_ss0|W_sv1] rows 0..127
__device__ float g_T3[(size_t)NNODE * 3 * 128];      // nv_d @ [W_vs1|W_vv1] rows 0..63

// GEMM outputs
__device__ float g_C1[(size_t)EDG * 256];
__device__ float g_C2[(size_t)EDG * 192];
__device__ float g_C3[(size_t)3 * EDG * 128];
__device__ float g_S2[(size_t)EDG * 128];
__device__ float g_V2[(size_t)3 * EDG * 64];
__device__ float g_We[(size_t)EDG * 192];

// B matrices bf16 [N x K] hi/lo
__device__ __nv_bfloat16 gB1h[256 * 128], gB1l[256 * 128];
__device__ __nv_bfloat16 gB2h[192 * 128], gB2l[192 * 128];
__device__ __nv_bfloat16 gB3h[128 * 64],  gB3l[128 * 64];
__device__ __nv_bfloat16 gBDh[128 * 128], gBDl[128 * 128];
__device__ __nv_bfloat16 gBEh[64 * 64],   gBEl[64 * 64];
__device__ __nv_bfloat16 gBFh[192 * 64],  gBFl[192 * 64];

// ---------------------------------------------------------------------------
__global__ void build_B(const float* __restrict__ Wa, const float* __restrict__ Wb,
                        int Na, int Nb, int K, int k0,
                        __nv_bfloat16* __restrict__ dh, __nv_bfloat16* __restrict__ dl)
{
    int N = Na + Nb;
    for (int idx = blockIdx.x * blockDim.x + threadIdx.x; idx < N * K; idx += gridDim.x * blockDim.x) {
        int n = idx / K, k = (idx - n * K) + k0;
        float w = (n < Na) ? Wa[(size_t)k * Na + n] : Wb[(size_t)k * Nb + (n - Na)];
        bsplit(w, &dh[idx], &dl[idx]);
    }
}

// ---------------------------------------------------------------------------
// Split-bf16 mma.sync GEMM:  C[M x N] = A @ B^T (+ table gather)
// TBL: 0 none, 1 C += T[ec[r]], 2 (d-major rows) C += T[ec[e]*3+d]
// ---------------------------------------------------------------------------
template <int N, int NT, int K, int TBL>
__global__ void __launch_bounds__(256) gemm_mma(
    const __nv_bfloat16* __restrict__ Ah, const __nv_bfloat16* __restrict__ Al,
    const __nv_bfloat16* __restrict__ Bh, const __nv_bfloat16* __restrict__ Bl,
    float* __restrict__ C, const float* __restrict__ T, const int* __restrict__ ecp)
{
    constexpr int KP = K + 8;
    constexpr int NTILES = NT / 8;
    constexpr int NGRP = NT / 16;
    extern __shared__ __nv_bfloat16 sB[];
    __nv_bfloat16* sBh = sB;
    __nv_bfloat16* sBl = sB + NT * KP;

    int tid = threadIdx.x;
    int wm = tid >> 5, lane = tid & 31;
    int n0 = blockIdx.y * NT;
    size_t m0 = (size_t)blockIdx.x * 128;

    for (int i = tid; i < NT * (K / 8); i += 256) {
        int n = i / (K / 8), kc = (i - n * (K / 8)) * 8;
        *(uint4*)&sBh[n * KP + kc] = *(const uint4*)&Bh[(size_t)(n0 + n) * K + kc];
        *(uint4*)&sBl[n * KP + kc] = *(const uint4*)&Bl[(size_t)(n0 + n) * K + kc];
    }
    __syncthreads();

    float acc[NTILES][4];
#pragma unroll
    for (int t = 0; t < NTILES; t++)
#pragma unroll
        for (int j = 0; j < 4; j++) acc[t][j] = 0.f;

    int q = lane & 3, rr = lane >> 2;
    const __nv_bfloat16* pAh = Ah + ((size_t)m0 + wm * 16 + rr) * K + q * 2;
    const __nv_bfloat16* pAl = Al + ((size_t)m0 + wm * 16 + rr) * K + q * 2;

    int lmrow = ((lane >> 4) << 3) + (lane & 7);
    int lmk = ((lane >> 3) & 1) * 8;
    uint32_t baseh = smem_u32(sBh) + (uint32_t)(lmrow * KP + lmk) * 2;
    uint32_t basel = smem_u32(sBl) + (uint32_t)(lmrow * KP + lmk) * 2;

    uint32_t ah[4], al[4];
    ah[0] = *(const uint32_t*)(pAh);
    ah[1] = *(const uint32_t*)(pAh + 8 * K);
    ah[2] = *(const uint32_t*)(pAh + 8);
    ah[3] = *(const uint32_t*)(pAh + 8 * K + 8);
    al[0] = *(const uint32_t*)(pAl);
    al[1] = *(const uint32_t*)(pAl + 8 * K);
    al[2] = *(const uint32_t*)(pAl + 8);
    al[3] = *(const uint32_t*)(pAl + 8 * K + 8);

#pragma unroll 4
    for (int k0 = 0; k0 < K; k0 += 16) {
        int kn = (k0 + 16 < K) ? (k0 + 16) : k0;
        uint32_t nh[4], nl[4];
        nh[0] = *(const uint32_t*)(pAh + kn);
        nh[1] = *(const uint32_t*)(pAh + 8 * K + kn);
        nh[2] = *(const uint32_t*)(pAh + kn + 8);
        nh[3] = *(const uint32_t*)(pAh + 8 * K + kn + 8);
        nl[0] = *(const uint32_t*)(pAl + kn);
        nl[1] = *(const uint32_t*)(pAl + 8 * K + kn);
        nl[2] = *(const uint32_t*)(pAl + kn + 8);
        nl[3] = *(const uint32_t*)(pAl + 8 * K + kn + 8);

#pragma unroll
        for (int g = 0; g < NGRP; g++) {
            uint32_t bh0, bh1, bh2, bh3, bl0, bl1, bl2, bl3;
            uint32_t adh = baseh + (uint32_t)(g * 16 * KP + k0) * 2;
            uint32_t adl = basel + (uint32_t)(g * 16 * KP + k0) * 2;
            asm volatile("ldmatrix.sync.aligned.m8n8.x4.shared.b16 {%0,%1,%2,%3}, [%4];"
                : "=r"(bh0), "=r"(bh1), "=r"(bh2), "=r"(bh3) : "r"(adh));
            asm volatile("ldmatrix.sync.aligned.m8n8.x4.shared.b16 {%0,%1,%2,%3}, [%4];"
                : "=r"(bl0), "=r"(bl1), "=r"(bl2), "=r"(bl3) : "r"(adl));
            mma_bf16(acc[2 * g], ah, bh0, bh1);
            mma_bf16(acc[2 * g], ah, bl0, bl1);
            mma_bf16(acc[2 * g], al, bh0, bh1);
            mma_bf16(acc[2 * g + 1], ah, bh2, bh3);
            mma_bf16(acc[2 * g + 1], ah, bl2, bl3);
            mma_bf16(acc[2 * g + 1], al, bh2, bh3);
        }
#pragma unroll
        for (int j = 0; j < 4; j++) { ah[j] = nh[j]; al[j] = nl[j]; }
    }

    size_t r = m0 + wm * 16 + rr;
    const float* t0 = nullptr;
    const float* t1 = nullptr;
    if (TBL == 1) {
        t0 = T + (size_t)ecp[r] * N;
        t1 = T + (size_t)ecp[r + 8] * N;
    } else if (TBL == 2) {
        int ri = (int)r;
        int d = ri / EDG, e0 = ri - d * EDG;
        t0 = T + ((size_t)ecp[e0] * 3 + d) * N;
        t1 = T + ((size_t)ecp[e0 + 8] * 3 + d) * N;
    }
#pragma unroll
    for (int t = 0; t < NTILES; t++) {
        int col = n0 + t * 8 + q * 2;
        float2 v0 = make_float2(acc[t][0], acc[t][1]);
        float2 v1 = make_float2(acc[t][2], acc[t][3]);
        if (TBL != 0) {
            float2 a0 = *(const float2*)(t0 + col);
            float2 a1 = *(const float2*)(t1 + col);
            v0.x += a0.x; v0.y += a0.y; v1.x += a1.x; v1.y += a1.y;
        }
        *(float2*)&C[r * N + col] = v0;
        *(float2*)&C[(r + 8) * N + col] = v1;
    }
}

// ---------------------------------------------------------------------------
// node LN
// ---------------------------------------------------------------------------
__global__ void __launch_bounds__(256) node_ln_kernel(
    const float* __restrict__ nf,
    const float* __restrict__ g_s, const float* __restrict__ b_s,
    const float* __restrict__ g_v)
{
    int node = blockIdx.x * 8 + (threadIdx.x >> 5);
    int lane = threadIdx.x & 31;
    if (node >= NNODE) return;
    const float* x = nf + (size_t)node * FDIM;

    float s0[4], sum = 0.f;
#pragma unroll
    for (int i = 0; i < 4; i++) { s0[i] = x[lane + 32 * i]; sum += s0[i]; }
    sum = warp_sum(sum);
    float mu = sum * (1.f / NS), var = 0.f;
#pragma unroll
    for (int i = 0; i < 4; i++) { float d = s0[i] - mu; var += d * d; }
    var = warp_sum(var) * (1.f / NS);
    float inv = rsqrtf(var + EPSV);
#pragma unroll
    for (int i = 0; i < 4; i++) {
        int k = lane + 32 * i;
        g_ns[node * NS + k] = (s0[i] - mu) * inv * g_s[k] + b_s[k];
    }
    float vv[6], ss = 0.f;
#pragma unroll
    for (int j = 0; j < 2; j++) {
        int cc = lane + 32 * j;
#pragma unroll
        for (int d = 0; d < 3; d++) { float t = x[NS + cc * 3 + d]; vv[j * 3 + d] = t; ss += t * t; }
    }
    ss = warp_sum(ss) * (1.f / NV);
    float inv2 = rsqrtf(ss + EPSV);
#pragma unroll
    for (int j = 0; j < 2; j++) {
        int cc = lane + 32 * j;
        float g = g_v[cc];
#pragma unroll
        for (int d = 0; d < 3; d++)
            g_nv[node * (NV * 3) + cc * 3 + d] = vv[j * 3 + d] * inv2 * g;
    }
}

// ---------------------------------------------------------------------------
// node tables (fp32)
// ---------------------------------------------------------------------------
__global__ void __launch_bounds__(256) table1_kernel(
    const float* __restrict__ W_ss0, const float* __restrict__ W_sv1)
{
    __shared__ float sns[8][NS];
    int base = blockIdx.x * 8, tid = threadIdx.x;
    int w = tid >> 5, lane = tid & 31;
#pragma unroll
    for (int i = 0; i < 4; i++) sns[w][lane + 32 * i] = g_ns[(base + w) * NS + lane + 32 * i];
    __syncthreads();
    int n = tid;  // 0..255
    float acc[8];
#pragma unroll
    for (int e = 0; e < 8; e++) acc[e] = 0.f;
    if (n < 192) {
        for (int k = 0; k < NS; k++) {
            float wv = W_ss0[k * 192 + n];
#pragma unroll
            for (int e = 0; e < 8; e++) acc[e] += sns[e][k] * wv;
        }
    } else {
        int f = n - 192;
        for (int k = 0; k < NS; k++) {
            float wv = W_sv1[k * 64 + f];
#pragma unroll
            for (int e = 0; e < 8; e++) acc[e] += sns[e][k] * wv;
        }
    }
#pragma unroll
    for (int e = 0; e < 8; e++) g_T1[(size_t)(base + e) * 256 + n] = acc[e];
}

__global__ void __launch_bounds__(256) table3_kernel(
    const float* __restrict__ W_vs1, const float* __restrict__ W_vv1)
{
    __shared__ float snv[8][NV * 3];
    int base = blockIdx.x * 8, tid = threadIdx.x;
    int w = tid >> 5, lane = tid & 31;
#pragma unroll
    for (int i = 0; i < 6; i++) snv[w][lane + 32 * i] = g_nv[(size_t)(base + w) * (NV * 3) + lane + 32 * i];
    __syncthreads();
    for (int it = tid; it < 384; it += 256) {
        int d = it >> 7, f = it & 127;
        const float* W = (f < 64) ? &W_vs1[f] : &W_vv1[f - 64];
        float acc[8];
#pragma unroll
        for (int e = 0; e < 8; e++) acc[e] = 0.f;
        for (int c = 0; c < NV; c++) {
            float wv = W[c * 64];
#pragma unroll
            for (int e = 0; e < 8; e++) acc[e] += snv[e][c * 3 + d] * wv;
        }
#pragma unroll
        for (int e = 0; e < 8; e++) g_T3[((size_t)(base + e) * 3 + d) * 128 + f] = acc[e];
    }
}

// ---------------------------------------------------------------------------
// residual (initializes out)
// ---------------------------------------------------------------------------
__global__ void __launch_bounds__(256) residual_kernel(
    const float* __restrict__ nf, const float* __restrict__ Wr_s,
    const float* __restrict__ Wr_v, float* __restrict__ out)
{
    __shared__ float snf[8][FDIM];
    int base = blockIdx.x * 8, tid = threadIdx.x;
    int w = tid >> 5, lane = tid & 31;
    int node = base + w;
    if (node < NNODE) {
        const float* x = nf + (size_t)node * FDIM;
#pragma unroll
        for (int i = 0; i < 10; i++) snf[w][lane + 32 * i] = x[lane + 32 * i];
    }
    __syncthreads();
    int nvalid = NNODE - base; if (nvalid > 8) nvalid = 8;
    for (int it = tid; it < FDIM; it += 256) {
        float acc[8];
#pragma unroll
        for (int e = 0; e < 8; e++) acc[e] = 0.f;
        if (it < NS) {
            for (int k = 0; k < NS; k++) {
                float wv = Wr_s[k * NS + it];
#pragma unroll
                for (int e = 0; e < 8; e++) acc[e] += snf[e][k] * wv;
            }
        } else {
            int idx = it - NS, f = idx / 3, d = idx - 3 * f;
            for (int cc = 0; cc < NV; cc++) {
                float wv = Wr_v[cc * NV + f];
#pragma unroll
                for (int e = 0; e < 8; e++) acc[e] += snf[e][NS + cc * 3 + d] * wv;
            }
        }
        for (int e = 0; e < nvalid; e++) out[(size_t)(base + e) * FDIM + it] = acc[e];
    }
}

// ---------------------------------------------------------------------------
// prep: edge LN + gathers -> split-bf16 A matrices (one warp per edge)
// ---------------------------------------------------------------------------
__global__ void __launch_bounds__(256) prep_kernel(
    const float* __restrict__ latents, const float* __restrict__ edge_features,
    const float* __restrict__ edge_sh, const int* __restrict__ edge_index,
    const int* __restrict__ active_edges,
    const float* __restrict__ g_s_e, const float* __restrict__ b_s_e,
    const float* __restrict__ g_v_e)
{
    int e = blockIdx.x * 8 + (threadIdx.x >> 5);
    int lane = threadIdx.x & 31;
    int ae = active_edges[e];
    int ec = edge_index[ae];
    if (lane == 0) g_ec[e] = ec;
    const float* xf = edge_features + (size_t)e * FDIM;

    float sx = edge_sh[(size_t)e * 4 + 1];
    float sy = edge_sh[(size_t)e * 4 + 2];
    float sz = edge_sh[(size_t)e * 4 + 3];

    // scalar LN: lane owns pairs (2*lane+64*i, 2*lane+1+64*i)
    {
        float2 s0[2];
        float sum = 0.f;
#pragma unroll
        for (int i = 0; i < 2; i++) {
            s0[i] = *(const float2*)(xf + 2 * lane + 64 * i);
            sum += s0[i].x + s0[i].y;
        }
        sum = warp_sum(sum);
        float mu = sum * (1.f / NS), var = 0.f;
#pragma unroll
        for (int i = 0; i < 2; i++) {
            float dx = s0[i].x - mu, dy = s0[i].y - mu;
            var += dx * dx + dy * dy;
        }
        var = warp_sum(var) * (1.f / NS);
        float inv = rsqrtf(var + EPSV);
#pragma unroll
        for (int i = 0; i < 2; i++) {
            int k = 2 * lane + 64 * i;
            float a = (s0[i].x - mu) * inv * g_s_e[k] + b_s_e[k];
            float b = (s0[i].y - mu) * inv * g_s_e[k + 1] + b_s_e[k + 1];
            __nv_bfloat162 H, L;
            bsplit2(a, b, &H, &L);
            *(__nv_bfloat162*)&g_Sh[(size_t)e * 128 + k] = H;
            *(__nv_bfloat162*)&g_Sl[(size_t)e * 128 + k] = L;
        }
    }

    // vector LN: lane owns channels 2*lane, 2*lane+1
    float ev0[3], ev1[3], nv0[3], nv1[3];
    {
        const float* vf = xf + NS + 6 * lane;
        float2 p0 = *(const float2*)(vf);
        float2 p1 = *(const float2*)(vf + 2);
        float2 p2 = *(const float2*)(vf + 4);
        ev0[0] = p0.x; ev0[1] = p0.y; ev0[2] = p1.x;
        ev1[0] = p1.y; ev1[1] = p2.x; ev1[2] = p2.y;
        float ss = ev0[0]*ev0[0] + ev0[1]*ev0[1] + ev0[2]*ev0[2]
                 + ev1[0]*ev1[0] + ev1[1]*ev1[1] + ev1[2]*ev1[2];
        ss = warp_sum(ss) * (1.f / NV);
        float inv2 = rsqrtf(ss + EPSV);
        float ga = g_v_e[2 * lane], gb = g_v_e[2 * lane + 1];
#pragma unroll
        for (int d = 0; d < 3; d++) {
            ev0[d] *= inv2 * ga;
            ev1[d] *= inv2 * gb;
            __nv_bfloat162 H, L;
            bsplit2(ev0[d], ev1[d], &H, &L);
            size_t o = ((size_t)d * EDG + e) * 64 + 2 * lane;
            *(__nv_bfloat162*)&g_Vh[o] = H;
            *(__nv_bfloat162*)&g_Vl[o] = L;
        }
    }
    // node vector gather (L2-resident table)
    {
        const float* nvp = g_nv + (size_t)ec * (NV * 3) + 6 * lane;
        float2 p0 = *(const float2*)(nvp);
        float2 p1 = *(const float2*)(nvp + 2);
        float2 p2 = *(const float2*)(nvp + 4);
        nv0[0] = p0.x; nv0[1] = p0.y; nv0[2] = p1.x;
        nv1[0] = p1.y; nv1[1] = p2.x; nv1[2] = p2.y;
    }
    // D: channels 0..63 node, 64..127 edge
    {
        float dn0 = (nv0[0] * sx + nv0[1] * sy + nv0[2] * sz) * INV_SQ3;
        float dn1 = (nv1[0] * sx + nv1[1] * sy + nv1[2] * sz) * INV_SQ3;
        float de0 = (ev0[0] * sx + ev0[1] * sy + ev0[2] * sz) * INV_SQ3;
        float de1 = (ev1[0] * sx + ev1[1] * sy + ev1[2] * sz) * INV_SQ3;
        __nv_bfloat162 H, L;
        bsplit2(dn0, dn1, &H, &L);
        *(__nv_bfloat162*)&g_Dh[(size_t)e * 128 + 2 * lane] = H;
        *(__nv_bfloat162*)&g_Dl[(size_t)e * 128 + 2 * lane] = L;
        bsplit2(de0, de1, &H, &L);
        *(__nv_bfloat162*)&g_Dh[(size_t)e * 128 + 64 + 2 * lane] = H;
        *(__nv_bfloat162*)&g_Dl[(size_t)e * 128 + 64 + 2 * lane] = L;
    }
    // latent gather
    {
        float2 p = *(const float2*)(latents + (size_t)ae * LATD + 2 * lane);
        __nv_bfloat162 H, L;
        bsplit2(p.x, p.y, &H, &L);
        *(__nv_bfloat162*)&g_Lh[(size_t)e * 64 + 2 * lane] = H;
        *(__nv_bfloat162*)&g_Ll[(size_t)e * 64 + 2 * lane] = L;
    }
}

// ---------------------------------------------------------------------------
// nonlin
// ---------------------------------------------------------------------------
__global__ void __launch_bounds__(256) nonlin_kernel(const float* __restrict__ edge_sh)
{
    int e = blockIdx.x * 8 + (threadIdx.x >> 5);
    int lane = threadIdx.x & 31;
    float sh0 = edge_sh[(size_t)e * 4 + 0];
    float sx = edge_sh[(size_t)e * 4 + 1];
    float sy = edge_sh[(size_t)e * 4 + 2];
    float sz = edge_sh[(size_t)e * 4 + 3];

    // silu: f pairs (2*lane + 64*i)
#pragma unroll
    for (int i = 0; i < 2; i++) {
        int f = 2 * lane + 64 * i;
        float2 c1 = *(const float2*)&g_C1[(size_t)e * 256 + f];
        float2 c2 = *(const float2*)&g_C2[(size_t)e * 192 + f];
        float oa = sh0 * c1.x + c2.x;
        float ob = sh0 * c1.y + c2.y;
        oa = oa / (1.f + expf(-oa));
        ob = ob / (1.f + expf(-ob));
        __nv_bfloat162 H, L;
        bsplit2(oa, ob, &H, &L);
        *(__nv_bfloat162*)&g_Uh[(size_t)e * 128 + f] = H;
        *(__nv_bfloat162*)&g_Ul[(size_t)e * 128 + f] = L;
    }
    // gates: f = 128 + 2*lane, +1
    float2 gc1 = *(const float2*)&g_C1[(size_t)e * 256 + 128 + 2 * lane];
    float2 gc2 = *(const float2*)&g_C2[(size_t)e * 192 + 128 + 2 * lane];
    float ga = sh0 * gc1.x + gc2.x;
    float gb = sh0 * gc1.y + gc2.y;
    ga = 1.f / (1.f + expf(-ga));
    gb = 1.f / (1.f + expf(-gb));

    // vector: channels 2*lane, 2*lane+1
    float2 P = *(const float2*)&g_C1[(size_t)e * 256 + 192 + 2 * lane];
    float2 Av[3], Aw[3];
#pragma unroll
    for (int d = 0; d < 3; d++) {
        size_t r = ((size_t)d * EDG + e) * 128;
        Av[d] = *(const float2*)&g_C3[r + 2 * lane];
        Aw[d] = *(const float2*)&g_C3[r + 64 + 2 * lane];
    }
    float shv[3] = { sx, sy, sz };
    float crx[3][2];
    crx[0][0] = (Aw[1].x * sz - Aw[2].x * sy) * INV_SQ2;
    crx[1][0] = (Aw[2].x * sx - Aw[0].x * sz) * INV_SQ2;
    crx[2][0] = (Aw[0].x * sy - Aw[1].x * sx) * INV_SQ2;
    crx[0][1] = (Aw[1].y * sz - Aw[2].y * sy) * INV_SQ2;
    crx[1][1] = (Aw[2].y * sx - Aw[0].y * sz) * INV_SQ2;
    crx[2][1] = (Aw[0].y * sy - Aw[1].y * sx) * INV_SQ2;
#pragma unroll
    for (int d = 0; d < 3; d++) {
        float va = (P.x * shv[d] + sh0 * Av[d].x + crx[d][0]) * ga;
        float vb = (P.y * shv[d] + sh0 * Av[d].y + crx[d][1]) * gb;
        __nv_bfloat162 H, L;
        bsplit2(va, vb, &H, &L);
        size_t o = ((size_t)d * EDG + e) * 64 + 2 * lane;
        *(__nv_bfloat162*)&g_Gh[o] = H;
        *(__nv_bfloat162*)&g_Gl[o] = L;
    }
}

// ---------------------------------------------------------------------------
// final: env-scale + atomic scatter
// ---------------------------------------------------------------------------
__global__ void __launch_bounds__(256) final_kernel(float* __restrict__ out)
{
    int e = blockIdx.x * 8 + (threadIdx.x >> 5);
    int lane = threadIdx.x & 31;
    int ec = g_ec[e];
    float* dst = out + (size_t)ec * FDIM;
#pragma unroll
    for (int i = 0; i < 4; i++) {
        int k = lane + 32 * i;
        float v = g_S2[(size_t)e * 128 + k] * g_We[(size_t)e * 192 + k];
        atomicAdd(&dst[k], AGG_SCALE * v);
    }
#pragma unroll
    for (int j = 0; j < 2; j++) {
        int f = lane + 32 * j;
        float wv = g_We[(size_t)e * 192 + 128 + f];
#pragma unroll
        for (int d = 0; d < 3; d++) {
            float v = g_V2[((size_t)d * EDG + e) * 64 + f] * wv;
            atomicAdd(&dst[NS + f * 3 + d], AGG_SCALE * v);
        }
    }
}

// ---------------------------------------------------------------------------
extern "C" void kernel_launch(void* const* d_in, const int* in_sizes, int n_in,
                              void* d_out, int out_size)
{
    const float* latents       = (const float*)d_in[0];
    const float* node_features = (const float*)d_in[1];
    const float* edge_features = (const float*)d_in[2];
    const float* edge_sh       = (const float*)d_in[3];
    const int*   edge_index    = (const int*)  d_in[4];
    const int*   active_edges  = (const int*)  d_in[6];
    const float* g_s_n = (const float*)d_in[7];
    const float* b_s_n = (const float*)d_in[8];
    const float* g_v_n = (const float*)d_in[9];
    const float* g_s_e = (const float*)d_in[10];
    const float* b_s_e = (const float*)d_in[11];
    const float* g_v_e = (const float*)d_in[12];
    const float* W_ss0 = (const float*)d_in[13];
    const float* W_vv0 = (const float*)d_in[14];
    const float* W_sv1 = (const float*)d_in[15];
    const float* W_vs1 = (const float*)d_in[16];
    const float* W_vv1 = (const float*)d_in[17];
    const float* Wp_s  = (const float*)d_in[18];
    const float* Wp_v  = (const float*)d_in[19];
    const float* W_env = (const float*)d_in[20];
    const float* Wr_s  = (const float*)d_in[21];
    const float* Wr_v  = (const float*)d_in[22];
    float* out = (float*)d_out;

    __nv_bfloat16 *B1h, *B1l, *B2h, *B2l, *B3h, *B3l, *BDh, *BDl, *BEh, *BEl, *BFh, *BFl;
    cudaGetSymbolAddress((void**)&B1h, gB1h); cudaGetSymbolAddress((void**)&B1l, gB1l);
    cudaGetSymbolAddress((void**)&B2h, gB2h); cudaGetSymbolAddress((void**)&B2l, gB2l);
    cudaGetSymbolAddress((void**)&B3h, gB3h); cudaGetSymbolAddress((void**)&B3l, gB3l);
    cudaGetSymbolAddress((void**)&BDh, gBDh); cudaGetSymbolAddress((void**)&BDl, gBDl);
    cudaGetSymbolAddress((void**)&BEh, gBEh); cudaGetSymbolAddress((void**)&BEl, gBEl);
    cudaGetSymbolAddress((void**)&BFh, gBFh); cudaGetSymbolAddress((void**)&BFl, gBFl);
    __nv_bfloat16 *Sh, *Sl, *Dh, *Dl, *Vh, *Vl, *Lh, *Ll, *Uh, *Ul, *Gh, *Gl;
    cudaGetSymbolAddress((void**)&Sh, g_Sh); cudaGetSymbolAddress((void**)&Sl, g_Sl);
    cudaGetSymbolAddress((void**)&Dh, g_Dh); cudaGetSymbolAddress((void**)&Dl, g_Dl);
    cudaGetSymbolAddress((void**)&Vh, g_Vh); cudaGetSymbolAddress((void**)&Vl, g_Vl);
    cudaGetSymbolAddress((void**)&Lh, g_Lh); cudaGetSymbolAddress((void**)&Ll, g_Ll);
    cudaGetSymbolAddress((void**)&Uh, g_Uh); cudaGetSymbolAddress((void**)&Ul, g_Ul);
    cudaGetSymbolAddress((void**)&Gh, g_Gh); cudaGetSymbolAddress((void**)&Gl, g_Gl);
    float *C1, *C2, *C3, *S2, *V2, *We, *T1, *T3;
    cudaGetSymbolAddress((void**)&C1, g_C1); cudaGetSymbolAddress((void**)&C2, g_C2);
    cudaGetSymbolAddress((void**)&C3, g_C3); cudaGetSymbolAddress((void**)&S2, g_S2);
    cudaGetSymbolAddress((void**)&V2, g_V2); cudaGetSymbolAddress((void**)&We, g_We);
    cudaGetSymbolAddress((void**)&T1, g_T1); cudaGetSymbolAddress((void**)&T3, g_T3);
    int* ecp;
    cudaGetSymbolAddress((void**)&ecp, g_ec);

    const int SM1 = 2 * 128 * 136 * 2;  // (NT=128,K=128) 69632
    const int SM2 = 2 * 96 * 136 * 2;   // 52224
    const int SM3 = 2 * 128 * 72 * 2;   // 36864
    const int SM5 = 2 * 64 * 72 * 2;    // 18432
    const int SM6 = 2 * 96 * 72 * 2;    // 27648
    cudaFuncSetAttribute(gemm_mma<256, 128, 128, 1>, cudaFuncAttributeMaxDynamicSharedMemorySize, SM1);
    cudaFuncSetAttribute(gemm_mma<192, 96, 128, 0>,  cudaFuncAttributeMaxDynamicSharedMemorySize, SM2);
    cudaFuncSetAttribute(gemm_mma<128, 128, 64, 2>,  cudaFuncAttributeMaxDynamicSharedMemorySize, SM3);
    cudaFuncSetAttribute(gemm_mma<128, 128, 128, 0>, cudaFuncAttributeMaxDynamicSharedMemorySize, SM1);
    cudaFuncSetAttribute(gemm_mma<64, 64, 64, 0>,    cudaFuncAttributeMaxDynamicSharedMemorySize, SM5);
    cudaFuncSetAttribute(gemm_mma<192, 96, 64, 0>,   cudaFuncAttributeMaxDynamicSharedMemorySize, SM6);

    // edge-side B matrices (k0 offsets select edge rows)
    build_B<<<64, 256>>>(W_ss0, W_sv1, 192, 64, 128, 128, B1h, B1l);
    build_B<<<64, 256>>>(W_vv0, nullptr, 192, 0, 128, 0, B2h, B2l);
    build_B<<<64, 256>>>(W_vs1, W_vv1, 64, 64, 64, 64, B3h, B3l);
    build_B<<<64, 256>>>(Wp_s, nullptr, 128, 0, 128, 0, BDh, BDl);
    build_B<<<64, 256>>>(Wp_v, nullptr, 64, 0, 64, 0, BEh, BEl);
    build_B<<<64, 256>>>(W_env, nullptr, 192, 0, 64, 0, BFh, BFl);

    node_ln_kernel<<<(NNODE + 7) / 8, 256>>>(node_features, g_s_n, b_s_n, g_v_n);
    residual_kernel<<<(NNODE + 7) / 8, 256>>>(node_features, Wr_s, Wr_v, out);
    table1_kernel<<<NNODE / 8, 256>>>(W_ss0, W_sv1);
    table3_kernel<<<NNODE / 8, 256>>>(W_vs1, W_vv1);
    prep_kernel<<<EDG / 8, 256>>>(latents, edge_features, edge_sh, edge_index, active_edges,
                                  g_s_e, b_s_e, g_v_e);

    gemm_mma<256, 128, 128, 1><<<dim3(EDG / 128, 2), 256, SM1>>>(Sh, Sl, B1h, B1l, C1, T1, ecp);
    gemm_mma<192, 96, 128, 0><<<dim3(EDG / 128, 2), 256, SM2>>>(Dh, Dl, B2h, B2l, C2, nullptr, nullptr);
    gemm_mma<128, 128, 64, 2><<<dim3(3 * EDG / 128, 1), 256, SM3>>>(Vh, Vl, B3h, B3l, C3, T3, ecp);

    nonlin_kernel<<<EDG / 8, 256>>>(edge_sh);

    gemm_mma<128, 128, 128, 0><<<dim3(EDG / 128, 1), 256, SM1>>>(Uh, Ul, BDh, BDl, S2, nullptr, nullptr);
    gemm_mma<64, 64, 64, 0><<<dim3(3 * EDG / 128, 1), 256, SM5>>>(Gh, Gl, BEh, BEl, V2, nullptr, nullptr);
    gemm_mma<192, 96, 64, 0><<<dim3(EDG / 128, 2), 256, SM6>>>(Lh, Ll, BFh, BFl, We, nullptr, nullptr);

    final_kernel<<<EDG / 8, 256>>>(out);
}